// round 16
// baseline (speedup 1.0000x reference)
#include <cuda_runtime.h>
#include <cuda_bf16.h>
#include <cstdint>
#include <cmath>

// Problem constants
#define D        512
#define NROWS    8192
#define BHALF    4096
#define NT       64                 // 128-row blocks per dim
#define NJ2      32                 // 256-col strips
#define NTILE2   1056               // sum over j2 of (2*j2+2)
#define NCHUNK   32
#define KCH      32                 // bf16 K elems per chunk
#define NCH      (D / KCH)          // 16 chunks
#define OPBA     8192               // A: 128 rows x 64 B
#define OPBB     16384              // B: 256 rows x 64 B
#define STAGEB   (OPBA + OPBB)      // 24576 B
#define TOTB     (2 * STAGEB)       // 49152 B = 48 KB static

// -------- device scratch --------
__device__ __align__(16) __nv_bfloat16 g_hi[NROWS * D];
__device__ float  g_sq[NROWS];
__device__ float  g_colpart[NCHUNK][D];
__device__ float  g_c16;
__device__ double g_partial[NTILE2];

// -------- helpers --------
__device__ __forceinline__ uint32_t smem_u32(const void* p) {
    uint32_t a;
    asm("{ .reg .u64 t; cvta.to.shared.u64 t, %1; cvt.u32.u64 %0, t; }" : "=r"(a) : "l"(p));
    return a;
}
__device__ __forceinline__ float ex2_approx(float x) {
    float y; asm("ex2.approx.ftz.f32 %0, %1;" : "=f"(y) : "f"(x)); return y;
}
#define LDSM4(r, a) \
    asm volatile("ldmatrix.sync.aligned.m8n8.x4.shared.b16 {%0,%1,%2,%3}, [%4];" \
        : "=r"((r)[0]), "=r"((r)[1]), "=r"((r)[2]), "=r"((r)[3]) : "r"(a))
#define MMA16816(c, A, b0, b1) \
    asm volatile("mma.sync.aligned.m16n8k16.row.col.f32.bf16.bf16.f32 " \
        "{%0,%1,%2,%3}, {%4,%5,%6,%7}, {%8,%9}, {%0,%1,%2,%3};" \
        : "+f"((c)[0]), "+f"((c)[1]), "+f"((c)[2]), "+f"((c)[3]) \
        : "r"((A)[0]), "r"((A)[1]), "r"((A)[2]), "r"((A)[3]), "r"(b0), "r"(b1))
#define CP_ASYNC16(dst, src) \
    asm volatile("cp.async.cg.shared.global [%0], [%1], 16;" :: "r"(dst), "l"(src) : "memory")
#define CP_COMMIT()  asm volatile("cp.async.commit_group;" ::: "memory")
#define CP_WAIT0()   asm volatile("cp.async.wait_group 0;" ::: "memory")

// -------- kernel 1: fused per-row sq-norm + bf16 hi split (one pass) --------
__global__ void k_prep(const float* __restrict__ src, const float* __restrict__ tgt) {
    int row  = blockIdx.x * 8 + (threadIdx.x >> 5);
    int lane = threadIdx.x & 31;
    const float* p = (row < BHALF) ? (src + (size_t)row * D)
                                   : (tgt + (size_t)(row - BHALF) * D);
    const float4* p4 = (const float4*)p;
    float s = 0.f;
    #pragma unroll
    for (int c = lane; c < D / 4; c += 32) {
        float4 v = p4[c];
        s += v.x * v.x + v.y * v.y + v.z * v.z + v.w * v.w;
        __nv_bfloat16 h0 = __float2bfloat16_rn(v.x);
        __nv_bfloat16 h1 = __float2bfloat16_rn(v.y);
        __nv_bfloat16 h2 = __float2bfloat16_rn(v.z);
        __nv_bfloat16 h3 = __float2bfloat16_rn(v.w);
        uint32_t p0 = (uint32_t)__bfloat16_as_ushort(h0) | ((uint32_t)__bfloat16_as_ushort(h1) << 16);
        uint32_t p1 = (uint32_t)__bfloat16_as_ushort(h2) | ((uint32_t)__bfloat16_as_ushort(h3) << 16);
        size_t elem = (size_t)row * D + (size_t)c * 4;
        *(uint2*)(g_hi + elem) = make_uint2(p0, p1);
    }
    #pragma unroll
    for (int o = 16; o; o >>= 1) s += __shfl_xor_sync(0xffffffffu, s, o);
    if (lane == 0) g_sq[row] = s;
}

// -------- kernel 2: column-sum partials --------
__global__ void k_colsum(const float* __restrict__ src, const float* __restrict__ tgt) {
    int c = blockIdx.x;
    int d = threadIdx.x;
    const float* base = (c < NCHUNK / 2) ? (src + (size_t)c * 256 * D)
                                         : (tgt + (size_t)(c - NCHUNK / 2) * 256 * D);
    float s = 0.f;
    for (int r = 0; r < 256; r++) s += base[(size_t)r * D + d];
    g_colpart[c][d] = s;
}

// -------- kernel 3: bandwidth scalar --------
__global__ void k_scalar() {
    int d = threadIdx.x;
    float cs = 0.f;
    #pragma unroll
    for (int c = 0; c < NCHUNK; c++) cs += g_colpart[c][d];
    double v  = (double)cs * (double)cs;
    double sq = 0.0;
    #pragma unroll
    for (int k = 0; k < NROWS / D; k++) sq += (double)g_sq[d + D * k];
    __shared__ double s1[512], s2[512];
    s1[d] = v; s2[d] = sq;
    __syncthreads();
    for (int o = 256; o; o >>= 1) {
        if (d < o) { s1[d] += s1[d + o]; s2[d] += s2[d + o]; }
        __syncthreads();
    }
    if (d == 0) {
        double n     = (double)NROWS;
        double sumL2 = 2.0 * n * s2[0] - 2.0 * s1[0];
        double bw    = sumL2 / (n * n - n) / 4.0;
        g_c16 = (float)(1.4426950408889634 / (bw * 16.0));
    }
}

// -------- kernel 4: HMMA bf16 GEMM, 128x256 CTA tile, 64x64 warp tile --------
// 256 threads, 48 KB static smem, 2-stage cp.async pipeline, 1 CTA/SM.
__global__ void __launch_bounds__(256) k_mmd_hmma() {
    __shared__ __align__(128) char sbuf[TOTB];

    int tid = threadIdx.x;
    int wid = tid >> 5, l = tid & 31;
    int warp_m = wid >> 2;          // 0..1 -> 64-row slab
    int warp_n = wid & 3;           // 0..3 -> 64-col slab

    // tile decode: blockIdx -> (j2, bi); j2 strip of 256 cols, bi in [0, 2*j2+1]
    int b = blockIdx.x;
    int j2 = (int)((sqrtf(4.f * (float)b + 1.f) - 1.f) * 0.5f);
    while ((j2 + 1) * (j2 + 2) <= b) j2++;
    while (j2 * (j2 + 1) > b) j2--;
    int bi = b - j2 * (j2 + 1);

    uint32_t sb = smem_u32(sbuf);
    const uint32_t arow = (uint32_t)bi * 128;
    const uint32_t brow = (uint32_t)j2 * 256;

    // loader: thread -> (r = tid>>2 in 0..63, seg = tid&3); 6 slots:
    //   A rows r, r+64 ; B rows r, r+64, r+128, r+192
    int r   = tid >> 2, seg = tid & 3;
    uint32_t atom = (uint32_t)seg ^ (((uint32_t)r >> 1) & 3);   // invariant under +64k rows
    uint32_t aoff = (uint32_t)r * 64 + (atom << 4);
    const __nv_bfloat16* gA = g_hi + ((size_t)(arow + r) * D + seg * 8);
    const __nv_bfloat16* gB = g_hi + ((size_t)(brow + r) * D + seg * 8);
    const size_t RS = (size_t)64 * D;   // +64 rows

    // per-lane ldmatrix row/swizzle
    uint32_t rowA = (uint32_t)warp_m * 64 + (l & 15);
    uint32_t swzA = (rowA >> 1) & 3;
    uint32_t offA = rowA * 64;
    uint32_t selA = (uint32_t)(l >> 4);
    uint32_t rowB = (uint32_t)warp_n * 64 + (l & 7) + ((l >> 4) << 3);
    uint32_t swzB = (rowB >> 1) & 3;
    uint32_t offB = rowB * 64;
    uint32_t selB = (uint32_t)((l >> 3) & 1);

    float c[4][8][4];
    #pragma unroll
    for (int mi = 0; mi < 4; mi++)
        #pragma unroll
        for (int nf = 0; nf < 8; nf++)
            #pragma unroll
            for (int q = 0; q < 4; q++) c[mi][nf][q] = 0.f;

    // prologue: issue chunk 0 into stage 0
    {
        uint32_t base = sb;
        CP_ASYNC16(base + aoff,                gA);
        CP_ASYNC16(base + 4096 + aoff,         gA + RS);
        CP_ASYNC16(base + OPBA + aoff,         gB);
        CP_ASYNC16(base + OPBA + 4096 + aoff,  gB + RS);
        CP_ASYNC16(base + OPBA + 8192 + aoff,  gB + 2 * RS);
        CP_ASYNC16(base + OPBA + 12288 + aoff, gB + 3 * RS);
        CP_COMMIT();
    }

    #pragma unroll 1
    for (int kc = 0; kc < NCH; kc++) {
        CP_WAIT0();          // chunk kc landed
        __syncthreads();     // visible to all; prev readers of other stage done

        // issue chunk kc+1 into the other stage
        if (kc + 1 < NCH) {
            uint32_t base = sb + (uint32_t)((kc + 1) & 1) * STAGEB;
            size_t ko = (size_t)(kc + 1) * KCH;
            CP_ASYNC16(base + aoff,                gA + ko);
            CP_ASYNC16(base + 4096 + aoff,         gA + RS + ko);
            CP_ASYNC16(base + OPBA + aoff,         gB + ko);
            CP_ASYNC16(base + OPBA + 4096 + aoff,  gB + RS + ko);
            CP_ASYNC16(base + OPBA + 8192 + aoff,  gB + 2 * RS + ko);
            CP_ASYNC16(base + OPBA + 12288 + aoff, gB + 3 * RS + ko);
            CP_COMMIT();
        }

        uint32_t st   = sb + (uint32_t)(kc & 1) * STAGEB;
        uint32_t ah_t = st + offA;
        uint32_t bh_t = st + OPBA + offB;

        #pragma unroll
        for (int ks = 0; ks < 2; ks++) {
            uint32_t atomA = ((uint32_t)ks * 2 + selA) ^ swzA;
            uint32_t atomB = ((uint32_t)ks * 2 + selB) ^ swzB;
            uint32_t Ah[4][4], Bh[4][4];
            #pragma unroll
            for (int mi = 0; mi < 4; mi++)
                LDSM4(Ah[mi], ah_t + (uint32_t)mi * 1024 + (atomA << 4));
            #pragma unroll
            for (int nj = 0; nj < 4; nj++)
                LDSM4(Bh[nj], bh_t + (uint32_t)nj * 1024 + (atomB << 4));
            #pragma unroll
            for (int mi = 0; mi < 4; mi++) {
                #pragma unroll
                for (int nf = 0; nf < 8; nf++) {
                    int nj = nf >> 1, h = (nf & 1) * 2;
                    MMA16816(c[mi][nf], Ah[mi], Bh[nj][h], Bh[nj][h + 1]);
                }
            }
        }
    }

    // per-warp weight: this warp covers 128-col block cb = 2*j2 + (warp_n>>1)
    int cb = 2 * j2 + (warp_n >> 1);
    float wt = (bi < cb) ? 2.f : ((bi == cb) ? 1.f : 0.f);
    if ((bi < NT / 2) != (cb < NT / 2)) wt = -wt;

    // epilogue: L2 -> u + u^2 + u^4 + u^8 + u^16
    float c16 = g_c16;
    float tsum = 0.f;
    #pragma unroll
    for (int mi = 0; mi < 4; mi++) {
        int r0 = warp_m * 64 + mi * 16 + (l >> 2);
        float sa0 = g_sq[arow + r0], sa1 = g_sq[arow + r0 + 8];
        #pragma unroll
        for (int nf = 0; nf < 8; nf++) {
            int j0 = warp_n * 64 + nf * 8 + 2 * (l & 3);
            float sb0 = g_sq[brow + j0], sb1 = g_sq[brow + j0 + 1];
            #pragma unroll
            for (int q = 0; q < 4; q++) {
                float sa  = (q < 2) ? sa0 : sa1;
                float sbv = (q & 1) ? sb1 : sb0;
                float L2  = sa + sbv - 2.f * c[mi][nf][q];
                float u   = ex2_approx(-L2 * c16);
                float u2 = u * u, u4 = u2 * u2, u8 = u4 * u4, u16 = u8 * u8;
                tsum += ((u + u2) + (u4 + u8)) + u16;
            }
        }
    }
    tsum *= wt;

    // warp shfl reduce, then 8 weighted partials via reused sbuf
    #pragma unroll
    for (int o = 16; o; o >>= 1) tsum += __shfl_xor_sync(0xffffffffu, tsum, o);
    float* red = (float*)sbuf;
    __syncthreads();                 // mainloop smem reads complete
    if (l == 0) red[wid] = tsum;
    __syncthreads();
    if (tid == 0) {
        float s = 0.f;
        #pragma unroll
        for (int w = 0; w < 8; w++) s += red[w];
        g_partial[blockIdx.x] = (double)s;
    }
}

// -------- kernel 5: deterministic final reduction --------
__global__ void k_final(float* __restrict__ out) {
    __shared__ double s[256];
    int tid = threadIdx.x;
    double acc = 0.0;
    for (int i = tid; i < NTILE2; i += 256) acc += g_partial[i];
    s[tid] = acc;
    __syncthreads();
    #pragma unroll
    for (int o = 128; o; o >>= 1) {
        if (tid < o) s[tid] += s[tid + o];
        __syncthreads();
    }
    if (tid == 0) out[0] = (float)(s[0] / ((double)BHALF * (double)BHALF));
}

extern "C" void kernel_launch(void* const* d_in, const int* in_sizes, int n_in,
                              void* d_out, int out_size) {
    const float* src = (const float*)d_in[0];
    const float* tgt = (const float*)d_in[1];
    float* out = (float*)d_out;

    k_prep<<<NROWS / 8, 256>>>(src, tgt);
    k_colsum<<<NCHUNK, 512>>>(src, tgt);
    k_scalar<<<1, 512>>>();
    k_mmd_hmma<<<NTILE2, 256>>>();
    k_final<<<1, 256>>>(out);
}